// round 12
// baseline (speedup 1.0000x reference)
#include <cuda_runtime.h>
#include <math.h>
#include <float.h>

#define BB 8
#define NN 4096
#define GC 16                 // grid cells per axis
#define NCELL (GC * GC * GC)  // 4096
#define RPC 8                 // rows per CTA (1 row per warp)
#define RCTAS (NN / RPC)      // 512 row-CTAs per batch
#define KC 5                  // cached points per lane/cell

static __device__ __constant__ float kEPS = 1e-5f;
static __device__ __constant__ float kF2  = 2.8853900817779268f; // FACT*log2(e)

// Scratch (device globals; fully overwritten every run)
__device__ float4 g_spts[BB][NN];             // cell-sorted pc2 points
__device__ int    g_cellstart[BB][NCELL + 1];
__device__ float  g_grid[BB][8];              // mbx,mby,mbz,icwx,icwy,icwz,minw
__device__ float  g_pcn[BB][3][NN];
__device__ float  g_dist[BB][NN];
__device__ float  g_dpart[BB][RCTAS];

__device__ __forceinline__ float frcp(float x) {
    float r; asm("rcp.approx.f32 %0, %1;" : "=f"(r) : "f"(x)); return r;
}
__device__ __forceinline__ float fex2(float x) {
    float r; asm("ex2.approx.f32 %0, %1;" : "=f"(r) : "f"(x)); return r;
}
__device__ __forceinline__ int clampi(int v, int lo, int hi) {
    return v < lo ? lo : (v > hi ? hi : v);
}

// ---------------------------------------------------------------------------
// Kernel 1: per-batch grid build (bbox, histogram, scan, scatter). 1 CTA/batch.
// ---------------------------------------------------------------------------
__global__ void __launch_bounds__(512)
cpnet_bin(const float* __restrict__ pc2) {
    const int b = blockIdx.x;
    const float* p2 = pc2 + (size_t)b * 4 * NN;
    const int tid = threadIdx.x;
    const int lane = tid & 31;
    const int w = tid >> 5;  // 16 warps

    __shared__ unsigned cnt[NCELL];
    __shared__ unsigned sstart[NCELL];
    __shared__ float red[16 * 6];
    __shared__ float gp[8];
    __shared__ unsigned wsum[16], woff[16];

    // ---- bbox ----
    float mnx = FLT_MAX, mny = FLT_MAX, mnz = FLT_MAX;
    float mxx = -FLT_MAX, mxy = -FLT_MAX, mxz = -FLT_MAX;
    for (int k = 0; k < NN / 512; ++k) {
        int i = k * 512 + tid;
        float x = p2[i], y = p2[NN + i], z = p2[2 * NN + i];
        mnx = fminf(mnx, x); mxx = fmaxf(mxx, x);
        mny = fminf(mny, y); mxy = fmaxf(mxy, y);
        mnz = fminf(mnz, z); mxz = fmaxf(mxz, z);
    }
    #pragma unroll
    for (int o = 16; o; o >>= 1) {
        mnx = fminf(mnx, __shfl_xor_sync(~0u, mnx, o));
        mny = fminf(mny, __shfl_xor_sync(~0u, mny, o));
        mnz = fminf(mnz, __shfl_xor_sync(~0u, mnz, o));
        mxx = fmaxf(mxx, __shfl_xor_sync(~0u, mxx, o));
        mxy = fmaxf(mxy, __shfl_xor_sync(~0u, mxy, o));
        mxz = fmaxf(mxz, __shfl_xor_sync(~0u, mxz, o));
    }
    if (lane == 0) {
        red[w] = mnx; red[16 + w] = mny; red[32 + w] = mnz;
        red[48 + w] = mxx; red[64 + w] = mxy; red[80 + w] = mxz;
    }
    __syncthreads();
    if (tid == 0) {
        float a0 = red[0], a1 = red[16], a2 = red[32];
        float b0 = red[48], b1 = red[64], b2 = red[80];
        for (int i = 1; i < 16; ++i) {
            a0 = fminf(a0, red[i]);      a1 = fminf(a1, red[16 + i]);
            a2 = fminf(a2, red[32 + i]); b0 = fmaxf(b0, red[48 + i]);
            b1 = fmaxf(b1, red[64 + i]); b2 = fmaxf(b2, red[80 + i]);
        }
        float wx = fmaxf(b0 - a0, 1e-6f);
        float wy = fmaxf(b1 - a1, 1e-6f);
        float wz = fmaxf(b2 - a2, 1e-6f);
        gp[0] = a0; gp[1] = a1; gp[2] = a2;
        gp[3] = (float)GC / wx; gp[4] = (float)GC / wy; gp[5] = (float)GC / wz;
        gp[6] = fminf(wx / GC, fminf(wy / GC, wz / GC));
        for (int i = 0; i < 7; ++i) g_grid[b][i] = gp[i];
    }
    __syncthreads();
    const float mbx = gp[0], mby = gp[1], mbz = gp[2];
    const float icwx = gp[3], icwy = gp[4], icwz = gp[5];

    // ---- histogram ----
    for (int k = 0; k < NCELL / 512; ++k) cnt[k * 512 + tid] = 0;
    __syncthreads();
    for (int k = 0; k < NN / 512; ++k) {
        int i = k * 512 + tid;
        float x = p2[i], y = p2[NN + i], z = p2[2 * NN + i];
        int cx = clampi((int)floorf((x - mbx) * icwx), 0, GC - 1);
        int cy = clampi((int)floorf((y - mby) * icwy), 0, GC - 1);
        int cz = clampi((int)floorf((z - mbz) * icwz), 0, GC - 1);
        atomicAdd(&cnt[cx + GC * (cy + GC * cz)], 1u);
    }
    __syncthreads();

    // ---- exclusive scan (8 cells/thread) ----
    unsigned v[8], tot = 0;
    #pragma unroll
    for (int j = 0; j < 8; ++j) { v[j] = cnt[tid * 8 + j]; tot += v[j]; }
    unsigned x = tot;
    #pragma unroll
    for (int o = 1; o < 32; o <<= 1) {
        unsigned t = __shfl_up_sync(~0u, x, o);
        if (lane >= o) x += t;
    }
    if (lane == 31) wsum[w] = x;
    __syncthreads();
    if (tid < 16) {
        unsigned y = wsum[tid];
        #pragma unroll
        for (int o = 1; o < 16; o <<= 1) {
            unsigned t = __shfl_up_sync(0xffffu, y, o);
            if (tid >= o) y += t;
        }
        woff[tid] = y - wsum[tid];
    }
    __syncthreads();
    unsigned run = (x - tot) + woff[w];
    #pragma unroll
    for (int j = 0; j < 8; ++j) {
        sstart[tid * 8 + j] = run;
        g_cellstart[b][tid * 8 + j] = (int)run;
        run += v[j];
    }
    if (tid == 511) g_cellstart[b][NCELL] = NN;
    __syncthreads();

    // ---- scatter (reuse cnt as cursor) ----
    for (int k = 0; k < NCELL / 512; ++k) cnt[k * 512 + tid] = 0;
    __syncthreads();
    for (int k = 0; k < NN / 512; ++k) {
        int i = k * 512 + tid;
        float xx = p2[i], yy = p2[NN + i], zz = p2[2 * NN + i];
        int cx = clampi((int)floorf((xx - mbx) * icwx), 0, GC - 1);
        int cy = clampi((int)floorf((yy - mby) * icwy), 0, GC - 1);
        int cz = clampi((int)floorf((zz - mbz) * icwz), 0, GC - 1);
        int cid = cx + GC * (cy + GC * cz);
        unsigned off = atomicAdd(&cnt[cid], 1u);
        g_spts[b][sstart[cid] + off] = make_float4(xx, yy, zz, 0.f);
    }
}

// ---------------------------------------------------------------------------
// Kernel 2: rows — one warp/row. Single scan with register cache of the
// 27-cell neighborhood; dense fallback reads sorted float4 points.
// ---------------------------------------------------------------------------
__global__ void __launch_bounds__(256)
cpnet_rows(const float* __restrict__ pc1, const float* __restrict__ pc2) {
    const int b = blockIdx.y;
    const int wid = threadIdx.x >> 5, lane = threadIdx.x & 31;
    const int n = blockIdx.x * RPC + wid;
    const float* p1 = pc1 + (size_t)b * 4 * NN;
    const float4* sp = g_spts[b];
    const int* cs = g_cellstart[b];

    const float mbx = g_grid[b][0], mby = g_grid[b][1], mbz = g_grid[b][2];
    const float icwx = g_grid[b][3], icwy = g_grid[b][4], icwz = g_grid[b][5];
    const float minw = g_grid[b][6];
    const float minw2 = minw * minw;

    const float px = p1[n], py = p1[NN + n], pz = p1[2 * NN + n];
    const int qx = clampi((int)floorf((px - mbx) * icwx), 0, GC - 1);
    const int qy = clampi((int)floorf((py - mby) * icwy), 0, GC - 1);
    const int qz = clampi((int)floorf((pz - mbz) * icwz), 0, GC - 1);

    // ---- single scan over own cell of the 27-neighborhood, caching points ----
    float cd[KC], cpx[KC], cpy[KC], cpz[KC];
    int s = 0, m = 0;
    {
        int cx = qx + lane % 3 - 1;
        int cy = qy + (lane / 3) % 3 - 1;
        int cz = qz + lane / 9 - 1;
        if (lane < 27 && (unsigned)cx < GC && (unsigned)cy < GC && (unsigned)cz < GC) {
            int cid = cx + GC * (cy + GC * cz);
            s = cs[cid];
            m = cs[cid + 1] - s;
        }
    }
    float dmin = FLT_MAX;
    #pragma unroll
    for (int k = 0; k < KC; ++k) {
        cd[k] = FLT_MAX; cpx[k] = 0.f; cpy[k] = 0.f; cpz[k] = 0.f;
        if (k < m) {
            float4 q = sp[s + k];
            float dx = px - q.x, dy = py - q.y, dz = pz - q.z;
            float d = fmaf(dx, dx, fmaf(dy, dy, dz * dz));
            cd[k] = d; cpx[k] = q.x; cpy[k] = q.y; cpz[k] = q.z;
            dmin = fminf(dmin, d);
        }
    }
    const bool ovf = (m > KC);
    if (ovf) {
        for (int k = KC; k < m; ++k) {
            float4 q = sp[s + k];
            float dx = px - q.x, dy = py - q.y, dz = pz - q.z;
            dmin = fminf(dmin, fmaf(dx, dx, fmaf(dy, dy, dz * dz)));
        }
    }
    #pragma unroll
    for (int o = 16; o; o >>= 1) dmin = fminf(dmin, __shfl_xor_sync(~0u, dmin, o));

    // NN exact iff closer than any point outside the 27-box (>= minw away).
    bool dense;
    float c = 0.f;
    if (dmin < minw2) {
        c = kF2 * frcp(fmaxf(dmin, kEPS));
        dense = (c <= 36.f) || (kF2 * frcp(c - 35.f) > minw2);
    } else {
        dense = true;
    }

    float Z = 0.f, ax = 0.f, ay = 0.f, az = 0.f;
    if (!dense) {
        #pragma unroll
        for (int k = 0; k < KC; ++k) {
            float ww = fex2(fmaf(frcp(fmaxf(cd[k], kEPS)), kF2, -c));
            Z += ww;
            ax = fmaf(ww, cpx[k], ax);
            ay = fmaf(ww, cpy[k], ay);
            az = fmaf(ww, cpz[k], az);
        }
        if (__any_sync(~0u, ovf)) {
            for (int k = KC; k < m; ++k) {
                float4 q = sp[s + k];
                float dx = px - q.x, dy = py - q.y, dz = pz - q.z;
                float d = fmaf(dx, dx, fmaf(dy, dy, dz * dz));
                float ww = fex2(fmaf(frcp(fmaxf(d, kEPS)), kF2, -c));
                Z += ww;
                ax = fmaf(ww, q.x, ax);
                ay = fmaf(ww, q.y, ay);
                az = fmaf(ww, q.z, az);
            }
        }
    } else {
        // Dense over the sorted float4 array (same set, coalesced vec loads)
        if (!(dmin < minw2)) {
            dmin = FLT_MAX;
            for (int mm = lane; mm < NN; mm += 32) {
                float4 q = sp[mm];
                float dx = px - q.x, dy = py - q.y, dz = pz - q.z;
                dmin = fminf(dmin, fmaf(dx, dx, fmaf(dy, dy, dz * dz)));
            }
            #pragma unroll
            for (int o = 16; o; o >>= 1) dmin = fminf(dmin, __shfl_xor_sync(~0u, dmin, o));
            c = kF2 * frcp(fmaxf(dmin, kEPS));
        }
        for (int mm = lane; mm < NN; mm += 32) {
            float4 q = sp[mm];
            float dx = px - q.x, dy = py - q.y, dz = pz - q.z;
            float d = fmaf(dx, dx, fmaf(dy, dy, dz * dz));
            float ww = fex2(fmaf(frcp(fmaxf(d, kEPS)), kF2, -c));
            Z += ww;
            ax = fmaf(ww, q.x, ax);
            ay = fmaf(ww, q.y, ay);
            az = fmaf(ww, q.z, az);
        }
    }

    #pragma unroll
    for (int o = 16; o; o >>= 1) {
        Z  += __shfl_xor_sync(~0u, Z,  o);
        ax += __shfl_xor_sync(~0u, ax, o);
        ay += __shfl_xor_sync(~0u, ay, o);
        az += __shfl_xor_sync(~0u, az, o);
    }

    __shared__ float sds[RPC];
    if (lane == 0) {
        float rz = 1.0f / Z;
        float q0 = ax * rz, q1 = ay * rz, q2 = az * rz;
        float dx = px - q0, dy = py - q1, dz = pz - q2;
        float dist = sqrtf(dx * dx + dy * dy + dz * dz);
        g_pcn[b][0][n] = q0; g_pcn[b][1][n] = q1; g_pcn[b][2][n] = q2;
        g_dist[b][n] = dist;
        sds[wid] = dist;
    }
    __syncthreads();
    if (threadIdx.x == 0) {
        float ssum = 0.f;
        #pragma unroll
        for (int i = 0; i < RPC; ++i) ssum += sds[i];
        g_dpart[b][blockIdx.x] = ssum;
    }
}

// ---------------------------------------------------------------------------
// Kernel 3: finalize — mean, moments, SVD, outputs. One CTA per batch;
// S[16] reduced entirely in smem (no global round trip before the SVD).
// ---------------------------------------------------------------------------
__global__ void __launch_bounds__(512)
cpnet_finalize(const float* __restrict__ pc1, float* __restrict__ out) {
    const int b = blockIdx.x;
    const float* p1 = pc1 + (size_t)b * 4 * NN;
    const int tid = threadIdx.x;
    const int lane = tid & 31;
    const int w = tid >> 5;  // 16 warps

    __shared__ float smW[16];
    __shared__ float smP[16][16];
    __shared__ double smS[16];

    // ---- mean from 512 row-CTA partials (1 load/thread) ----
    float v = g_dpart[b][tid];
    #pragma unroll
    for (int o = 16; o; o >>= 1) v += __shfl_xor_sync(~0u, v, o);
    if (lane == 0) smW[w] = v;
    __syncthreads();
    double ms = 0.0;
    #pragma unroll
    for (int i = 0; i < 16; ++i) ms += (double)smW[i];
    const float mean = (float)(ms * (1.0 / (double)NN));

    // ---- 16 uncentered moments over all 4096 elements ----
    float P[16];
    #pragma unroll
    for (int i = 0; i < 16; ++i) P[i] = 0.f;
    #pragma unroll
    for (int k = 0; k < NN / 512; ++k) {
        int n = k * 512 + tid;
        float dist = g_dist[b][n];
        float z = (dist - mean - kEPS) * 1e10f;
        float ind = 1.0f / (1.0f + __expf(z));
        float axx = p1[n], ayy = p1[NN + n], azz = p1[2 * NN + n];
        float bx = g_pcn[b][0][n], by = g_pcn[b][1][n], bz = g_pcn[b][2][n];
        float iax = ind * axx, iay = ind * ayy, iaz = ind * azz;
        P[0] += ind;
        P[1] += iax; P[2] += iay; P[3] += iaz;
        P[4] += ind * bx; P[5] += ind * by; P[6] += ind * bz;
        P[7]  += iax * bx; P[8]  += iax * by; P[9]  += iax * bz;
        P[10] += iay * bx; P[11] += iay * by; P[12] += iay * bz;
        P[13] += iaz * bx; P[14] += iaz * by; P[15] += iaz * bz;
    }
    #pragma unroll
    for (int o = 16; o; o >>= 1)
        #pragma unroll
        for (int i = 0; i < 16; ++i)
            P[i] += __shfl_xor_sync(~0u, P[i], o);
    if (lane == 0) {
        #pragma unroll
        for (int i = 0; i < 16; ++i) smP[w][i] = P[i];
    }
    __syncthreads();
    if (w == 0 && lane < 16) {
        double ssum = 0.0;
        #pragma unroll
        for (int ww = 0; ww < 16; ++ww) ssum += (double)smP[ww][lane];
        smS[lane] = ssum;
    }
    __syncthreads();
    if (tid != 0) return;

    // ---- serial 3x3 tail (fp32 + MUFU) ----
    double S[16];
    #pragma unroll
    for (int i = 0; i < 16; ++i) S[i] = smS[i];

    const double sw = S[0];
    const double inv_sw = 1.0 / sw;
    float c1v[3] = {(float)(S[1] * inv_sw), (float)(S[2] * inv_sw), (float)(S[3] * inv_sw)};
    float c2v[3] = {(float)(S[4] * inv_sw), (float)(S[5] * inv_sw), (float)(S[6] * inv_sw)};
    float H[3][3];
    #pragma unroll
    for (int i = 0; i < 3; ++i)
        #pragma unroll
        for (int j = 0; j < 3; ++j)
            H[i][j] = (float)(S[7 + i * 3 + j] - S[1 + i] * S[4 + j] * inv_sw);

    float G[3][3];
    #pragma unroll
    for (int i = 0; i < 3; ++i)
        #pragma unroll
        for (int j = 0; j < 3; ++j)
            G[i][j] = H[0][i] * H[0][j] + H[1][i] * H[1][j] + H[2][i] * H[2][j];
    float V[3][3] = {{1, 0, 0}, {0, 1, 0}, {0, 0, 1}};
    const int PP[3] = {0, 0, 1}, QQ[3] = {1, 2, 2};
    #pragma unroll
    for (int it = 0; it < 18; ++it) {
        int p = PP[it % 3], q = QQ[it % 3];
        float apq = G[p][q];
        if (fabsf(apq) > 1e-25f) {
            float theta = (G[q][q] - G[p][p]) / (2.0f * apq);
            float t = copysignf(1.0f, theta) / (fabsf(theta) + sqrtf(theta * theta + 1.0f));
            float c = rsqrtf(t * t + 1.0f);
            float sn = t * c;
            #pragma unroll
            for (int k = 0; k < 3; ++k) {
                float gkp = G[k][p], gkq = G[k][q];
                G[k][p] = c * gkp - sn * gkq;
                G[k][q] = sn * gkp + c * gkq;
            }
            #pragma unroll
            for (int k = 0; k < 3; ++k) {
                float gpk = G[p][k], gqk = G[q][k];
                G[p][k] = c * gpk - sn * gqk;
                G[q][k] = sn * gpk + c * gqk;
            }
            #pragma unroll
            for (int k = 0; k < 3; ++k) {
                float vkp = V[k][p], vkq = V[k][q];
                V[k][p] = c * vkp - sn * vkq;
                V[k][q] = sn * vkp + c * vkq;
            }
        }
    }
    float ev[3] = {G[0][0], G[1][1], G[2][2]};
    #pragma unroll
    for (int a = 0; a < 2; ++a)
        #pragma unroll
        for (int bc = 1; bc < 3; ++bc)
            if (bc > a && ev[bc] > ev[a]) {
                float te = ev[a]; ev[a] = ev[bc]; ev[bc] = te;
                #pragma unroll
                for (int k = 0; k < 3; ++k) {
                    float tv = V[k][a]; V[k][a] = V[k][bc]; V[k][bc] = tv;
                }
            }
    float U[3][3];
    #pragma unroll
    for (int j = 0; j < 3; ++j) {
        float sig = sqrtf(fmaxf(ev[j], 0.f));
        float inv = (sig > 1e-20f) ? (1.0f / sig) : 0.f;
        #pragma unroll
        for (int i = 0; i < 3; ++i)
            U[i][j] = (H[i][0] * V[0][j] + H[i][1] * V[1][j] + H[i][2] * V[2][j]) * inv;
    }
    auto det3 = [](float M[3][3]) {
        return M[0][0] * (M[1][1] * M[2][2] - M[1][2] * M[2][1])
             - M[0][1] * (M[1][0] * M[2][2] - M[1][2] * M[2][0])
             + M[0][2] * (M[1][0] * M[2][1] - M[1][1] * M[2][0]);
    };
    float sign = (det3(U) * det3(V) < 0.f) ? -1.f : 1.f;
    V[0][2] *= sign; V[1][2] *= sign; V[2][2] *= sign;
    float R[3][3];
    #pragma unroll
    for (int i = 0; i < 3; ++i)
        #pragma unroll
        for (int j = 0; j < 3; ++j)
            R[i][j] = V[i][0] * U[j][0] + V[i][1] * U[j][1] + V[i][2] * U[j][2];
    float tt[3];
    #pragma unroll
    for (int i = 0; i < 3; ++i)
        tt[i] = c2v[i] - (R[i][0] * c1v[0] + R[i][1] * c1v[1] + R[i][2] * c1v[2]);

    float* T = out + b * 16;
    #pragma unroll
    for (int i = 0; i < 3; ++i) {
        T[i * 4 + 0] = R[i][0];
        T[i * 4 + 1] = R[i][1];
        T[i * 4 + 2] = R[i][2];
        T[i * 4 + 3] = tt[i];
    }
    T[12] = 0.f; T[13] = 0.f; T[14] = 0.f; T[15] = 1.f;

    auto sgn = [](float x) { return x >= 0.f ? 1.f : -1.f; };
    float qw = 0.5f * sqrtf(fmaxf(1.f + R[0][0] + R[1][1] + R[2][2], 1e-12f));
    float qx = 0.5f * sqrtf(fmaxf(1.f + R[0][0] - R[1][1] - R[2][2], 1e-12f)) * sgn(R[2][1] - R[1][2]);
    float qy = 0.5f * sqrtf(fmaxf(1.f - R[0][0] + R[1][1] - R[2][2], 1e-12f)) * sgn(R[0][2] - R[2][0]);
    float qz = 0.5f * sqrtf(fmaxf(1.f - R[0][0] - R[1][1] + R[2][2], 1e-12f)) * sgn(R[1][0] - R[0][1]);
    float* qo = out + BB * 16 + b * 4;
    qo[0] = qw; qo[1] = qx; qo[2] = qy; qo[3] = qz;
    float* to = out + BB * 16 + BB * 4 + b * 3;
    to[0] = tt[0]; to[1] = tt[1]; to[2] = tt[2];
}

// ---------------------------------------------------------------------------
extern "C" void kernel_launch(void* const* d_in, const int* in_sizes, int n_in,
                              void* d_out, int out_size) {
    const float* pc1 = (const float*)d_in[0];
    const float* pc2 = (const float*)d_in[1];
    float* out = (float*)d_out;

    cpnet_bin<<<BB, 512>>>(pc2);
    dim3 rgrid(RCTAS, BB);   // 512 x 8 CTAs, 8 warps = 8 rows each
    cpnet_rows<<<rgrid, 256>>>(pc1, pc2);
    cpnet_finalize<<<BB, 512>>>(pc1, out);
}

// round 13
// speedup vs baseline: 1.0803x; 1.0803x over previous
#include <cuda_runtime.h>
#include <math.h>
#include <float.h>

#define BB 8
#define NN 4096
#define GC 16                 // grid cells per axis
#define NCELL (GC * GC * GC)  // 4096
#define RPC 8                 // rows per CTA (1 row per warp)
#define RCTAS (NN / RPC)      // 512 row-CTAs per batch
#define KC 5                  // cached points per lane/cell

static __device__ __constant__ float kEPS = 1e-5f;
static __device__ __constant__ float kF2  = 2.8853900817779268f; // FACT*log2(e)

// Scratch (device globals; fully overwritten every run)
__device__ float4 g_spts[BB][NN];             // cell-sorted pc2 points
__device__ int    g_cellstart[BB][NCELL + 1];
__device__ float  g_grid[BB][8];              // mbx,mby,mbz,icwx,icwy,icwz,minw
__device__ float  g_pcn[BB][3][NN];
__device__ float  g_dist[BB][NN];
__device__ float  g_dpart[BB][RCTAS];
__device__ float  g_mpart[BB][8][16];

__device__ __forceinline__ float frcp(float x) {
    float r; asm("rcp.approx.f32 %0, %1;" : "=f"(r) : "f"(x)); return r;
}
__device__ __forceinline__ float fex2(float x) {
    float r; asm("ex2.approx.f32 %0, %1;" : "=f"(r) : "f"(x)); return r;
}
__device__ __forceinline__ int clampi(int v, int lo, int hi) {
    return v < lo ? lo : (v > hi ? hi : v);
}

// ---------------------------------------------------------------------------
// Kernel 1: grid build. 1 CTA/batch, 1024 threads, 4 points/thread held in
// REGISTERS across all phases (single global read of pc2).
// ---------------------------------------------------------------------------
__global__ void __launch_bounds__(1024)
cpnet_bin(const float* __restrict__ pc2) {
    const int b = blockIdx.x;
    const float* p2 = pc2 + (size_t)b * 4 * NN;
    const int tid = threadIdx.x;
    const int lane = tid & 31;
    const int w = tid >> 5;  // 32 warps

    __shared__ unsigned cnt[NCELL];     // 16KB
    __shared__ unsigned sstart[NCELL];  // 16KB
    __shared__ float red[32 * 6];
    __shared__ float gp[8];
    __shared__ unsigned wsum[32], woff[32];

    // ---- load 4 points/thread into registers; bbox on the fly ----
    float ptx[4], pty[4], ptz[4];
    float mnx = FLT_MAX, mny = FLT_MAX, mnz = FLT_MAX;
    float mxx = -FLT_MAX, mxy = -FLT_MAX, mxz = -FLT_MAX;
    #pragma unroll
    for (int k = 0; k < 4; ++k) {
        int i = k * 1024 + tid;
        float x = p2[i], y = p2[NN + i], z = p2[2 * NN + i];
        ptx[k] = x; pty[k] = y; ptz[k] = z;
        mnx = fminf(mnx, x); mxx = fmaxf(mxx, x);
        mny = fminf(mny, y); mxy = fmaxf(mxy, y);
        mnz = fminf(mnz, z); mxz = fmaxf(mxz, z);
    }
    #pragma unroll
    for (int o = 16; o; o >>= 1) {
        mnx = fminf(mnx, __shfl_xor_sync(~0u, mnx, o));
        mny = fminf(mny, __shfl_xor_sync(~0u, mny, o));
        mnz = fminf(mnz, __shfl_xor_sync(~0u, mnz, o));
        mxx = fmaxf(mxx, __shfl_xor_sync(~0u, mxx, o));
        mxy = fmaxf(mxy, __shfl_xor_sync(~0u, mxy, o));
        mxz = fmaxf(mxz, __shfl_xor_sync(~0u, mxz, o));
    }
    if (lane == 0) {
        red[w] = mnx; red[32 + w] = mny; red[64 + w] = mnz;
        red[96 + w] = mxx; red[128 + w] = mxy; red[160 + w] = mxz;
    }
    // zero histogram while bbox reduction settles
    #pragma unroll
    for (int k = 0; k < NCELL / 1024; ++k) cnt[k * 1024 + tid] = 0;
    __syncthreads();
    if (tid == 0) {
        float a0 = red[0], a1 = red[32], a2 = red[64];
        float b0 = red[96], b1 = red[128], b2 = red[160];
        for (int i = 1; i < 32; ++i) {
            a0 = fminf(a0, red[i]);       a1 = fminf(a1, red[32 + i]);
            a2 = fminf(a2, red[64 + i]);  b0 = fmaxf(b0, red[96 + i]);
            b1 = fmaxf(b1, red[128 + i]); b2 = fmaxf(b2, red[160 + i]);
        }
        float wx = fmaxf(b0 - a0, 1e-6f);
        float wy = fmaxf(b1 - a1, 1e-6f);
        float wz = fmaxf(b2 - a2, 1e-6f);
        gp[0] = a0; gp[1] = a1; gp[2] = a2;
        gp[3] = (float)GC / wx; gp[4] = (float)GC / wy; gp[5] = (float)GC / wz;
        gp[6] = fminf(wx / GC, fminf(wy / GC, wz / GC));
        for (int i = 0; i < 7; ++i) g_grid[b][i] = gp[i];
    }
    __syncthreads();
    const float mbx = gp[0], mby = gp[1], mbz = gp[2];
    const float icwx = gp[3], icwy = gp[4], icwz = gp[5];

    // ---- histogram from registers (cell ids cached) ----
    int cell[4];
    #pragma unroll
    for (int k = 0; k < 4; ++k) {
        int cx = clampi((int)floorf((ptx[k] - mbx) * icwx), 0, GC - 1);
        int cy = clampi((int)floorf((pty[k] - mby) * icwy), 0, GC - 1);
        int cz = clampi((int)floorf((ptz[k] - mbz) * icwz), 0, GC - 1);
        cell[k] = cx + GC * (cy + GC * cz);
        atomicAdd(&cnt[cell[k]], 1u);
    }
    __syncthreads();

    // ---- exclusive scan (4 cells/thread, 1024 threads) ----
    unsigned v[4], tot = 0;
    #pragma unroll
    for (int j = 0; j < 4; ++j) { v[j] = cnt[tid * 4 + j]; tot += v[j]; }
    unsigned x = tot;
    #pragma unroll
    for (int o = 1; o < 32; o <<= 1) {
        unsigned t = __shfl_up_sync(~0u, x, o);
        if (lane >= o) x += t;
    }
    if (lane == 31) wsum[w] = x;
    __syncthreads();
    if (tid < 32) {
        unsigned y = wsum[tid];
        #pragma unroll
        for (int o = 1; o < 32; o <<= 1) {
            unsigned t = __shfl_up_sync(~0u, y, o);
            if (tid >= o) y += t;
        }
        woff[tid] = y - wsum[tid];
    }
    __syncthreads();
    unsigned run = (x - tot) + woff[w];
    #pragma unroll
    for (int j = 0; j < 4; ++j) {
        sstart[tid * 4 + j] = run;
        g_cellstart[b][tid * 4 + j] = (int)run;
        run += v[j];
    }
    if (tid == 1023) g_cellstart[b][NCELL] = NN;
    __syncthreads();

    // ---- reset cursors, scatter from registers ----
    #pragma unroll
    for (int k = 0; k < NCELL / 1024; ++k) cnt[k * 1024 + tid] = 0;
    __syncthreads();
    #pragma unroll
    for (int k = 0; k < 4; ++k) {
        unsigned off = atomicAdd(&cnt[cell[k]], 1u);
        g_spts[b][sstart[cell[k]] + off] = make_float4(ptx[k], pty[k], ptz[k], 0.f);
    }
}

// ---------------------------------------------------------------------------
// Kernel 2: rows — one warp/row. Single scan with register cache of the
// 27-cell neighborhood; dense fallback reads sorted float4 points.
// ---------------------------------------------------------------------------
__global__ void __launch_bounds__(256)
cpnet_rows(const float* __restrict__ pc1, const float* __restrict__ pc2) {
    const int b = blockIdx.y;
    const int wid = threadIdx.x >> 5, lane = threadIdx.x & 31;
    const int n = blockIdx.x * RPC + wid;
    const float* p1 = pc1 + (size_t)b * 4 * NN;
    const float4* sp = g_spts[b];
    const int* cs = g_cellstart[b];

    const float mbx = g_grid[b][0], mby = g_grid[b][1], mbz = g_grid[b][2];
    const float icwx = g_grid[b][3], icwy = g_grid[b][4], icwz = g_grid[b][5];
    const float minw = g_grid[b][6];
    const float minw2 = minw * minw;

    const float px = p1[n], py = p1[NN + n], pz = p1[2 * NN + n];
    const int qx = clampi((int)floorf((px - mbx) * icwx), 0, GC - 1);
    const int qy = clampi((int)floorf((py - mby) * icwy), 0, GC - 1);
    const int qz = clampi((int)floorf((pz - mbz) * icwz), 0, GC - 1);

    // ---- single scan over own cell of the 27-neighborhood, caching points ----
    float cd[KC], cpx[KC], cpy[KC], cpz[KC];
    int s = 0, m = 0;
    {
        int cx = qx + lane % 3 - 1;
        int cy = qy + (lane / 3) % 3 - 1;
        int cz = qz + lane / 9 - 1;
        if (lane < 27 && (unsigned)cx < GC && (unsigned)cy < GC && (unsigned)cz < GC) {
            int cid = cx + GC * (cy + GC * cz);
            s = cs[cid];
            m = cs[cid + 1] - s;
        }
    }
    float dmin = FLT_MAX;
    #pragma unroll
    for (int k = 0; k < KC; ++k) {
        cd[k] = FLT_MAX; cpx[k] = 0.f; cpy[k] = 0.f; cpz[k] = 0.f;
        if (k < m) {
            float4 q = sp[s + k];
            float dx = px - q.x, dy = py - q.y, dz = pz - q.z;
            float d = fmaf(dx, dx, fmaf(dy, dy, dz * dz));
            cd[k] = d; cpx[k] = q.x; cpy[k] = q.y; cpz[k] = q.z;
            dmin = fminf(dmin, d);
        }
    }
    const bool ovf = (m > KC);
    if (ovf) {
        for (int k = KC; k < m; ++k) {
            float4 q = sp[s + k];
            float dx = px - q.x, dy = py - q.y, dz = pz - q.z;
            dmin = fminf(dmin, fmaf(dx, dx, fmaf(dy, dy, dz * dz)));
        }
    }
    #pragma unroll
    for (int o = 16; o; o >>= 1) dmin = fminf(dmin, __shfl_xor_sync(~0u, dmin, o));

    // NN exact iff closer than any point outside the 27-box (>= minw away).
    bool dense;
    float c = 0.f;
    if (dmin < minw2) {
        c = kF2 * frcp(fmaxf(dmin, kEPS));
        dense = (c <= 36.f) || (kF2 * frcp(c - 35.f) > minw2);
    } else {
        dense = true;
    }

    float Z = 0.f, ax = 0.f, ay = 0.f, az = 0.f;
    if (!dense) {
        #pragma unroll
        for (int k = 0; k < KC; ++k) {
            float ww = fex2(fmaf(frcp(fmaxf(cd[k], kEPS)), kF2, -c));
            Z += ww;
            ax = fmaf(ww, cpx[k], ax);
            ay = fmaf(ww, cpy[k], ay);
            az = fmaf(ww, cpz[k], az);
        }
        if (__any_sync(~0u, ovf)) {
            for (int k = KC; k < m; ++k) {
                float4 q = sp[s + k];
                float dx = px - q.x, dy = py - q.y, dz = pz - q.z;
                float d = fmaf(dx, dx, fmaf(dy, dy, dz * dz));
                float ww = fex2(fmaf(frcp(fmaxf(d, kEPS)), kF2, -c));
                Z += ww;
                ax = fmaf(ww, q.x, ax);
                ay = fmaf(ww, q.y, ay);
                az = fmaf(ww, q.z, az);
            }
        }
    } else {
        if (!(dmin < minw2)) {
            dmin = FLT_MAX;
            for (int mm = lane; mm < NN; mm += 32) {
                float4 q = sp[mm];
                float dx = px - q.x, dy = py - q.y, dz = pz - q.z;
                dmin = fminf(dmin, fmaf(dx, dx, fmaf(dy, dy, dz * dz)));
            }
            #pragma unroll
            for (int o = 16; o; o >>= 1) dmin = fminf(dmin, __shfl_xor_sync(~0u, dmin, o));
            c = kF2 * frcp(fmaxf(dmin, kEPS));
        }
        for (int mm = lane; mm < NN; mm += 32) {
            float4 q = sp[mm];
            float dx = px - q.x, dy = py - q.y, dz = pz - q.z;
            float d = fmaf(dx, dx, fmaf(dy, dy, dz * dz));
            float ww = fex2(fmaf(frcp(fmaxf(d, kEPS)), kF2, -c));
            Z += ww;
            ax = fmaf(ww, q.x, ax);
            ay = fmaf(ww, q.y, ay);
            az = fmaf(ww, q.z, az);
        }
    }

    #pragma unroll
    for (int o = 16; o; o >>= 1) {
        Z  += __shfl_xor_sync(~0u, Z,  o);
        ax += __shfl_xor_sync(~0u, ax, o);
        ay += __shfl_xor_sync(~0u, ay, o);
        az += __shfl_xor_sync(~0u, az, o);
    }

    __shared__ float sds[RPC];
    if (lane == 0) {
        float rz = 1.0f / Z;
        float q0 = ax * rz, q1 = ay * rz, q2 = az * rz;
        float dx = px - q0, dy = py - q1, dz = pz - q2;
        float dist = sqrtf(dx * dx + dy * dy + dz * dz);
        g_pcn[b][0][n] = q0; g_pcn[b][1][n] = q1; g_pcn[b][2][n] = q2;
        g_dist[b][n] = dist;
        sds[wid] = dist;
    }
    __syncthreads();
    if (threadIdx.x == 0) {
        float ssum = 0.f;
        #pragma unroll
        for (int i = 0; i < RPC; ++i) ssum += sds[i];
        g_dpart[b][blockIdx.x] = ssum;
    }
}

// ---------------------------------------------------------------------------
// Kernel 3: moments per slice (mean from g_dpart partials).
// ---------------------------------------------------------------------------
__global__ void __launch_bounds__(256)
cpnet_moments(const float* __restrict__ pc1) {
    const int b = blockIdx.y;
    const int slice = blockIdx.x;
    const float* p1 = pc1 + (size_t)b * 4 * NN;
    const int tid = threadIdx.x;
    const int lane = tid & 31;
    const int w = tid >> 5;

    __shared__ float smW[8];
    __shared__ float smP[8][16];

    float v = g_dpart[b][tid] + g_dpart[b][tid + 256];
    #pragma unroll
    for (int o = 16; o; o >>= 1) v += __shfl_xor_sync(~0u, v, o);
    if (lane == 0) smW[w] = v;
    __syncthreads();
    double ms = 0.0;
    #pragma unroll
    for (int i = 0; i < 8; ++i) ms += (double)smW[i];
    const float mean = (float)(ms * (1.0 / (double)NN));

    float P[16];
    #pragma unroll
    for (int i = 0; i < 16; ++i) P[i] = 0.f;
    #pragma unroll
    for (int k = 0; k < 2; ++k) {
        int n = slice * 512 + k * 256 + tid;
        float dist = g_dist[b][n];
        float z = (dist - mean - kEPS) * 1e10f;
        float ind = 1.0f / (1.0f + __expf(z));
        float axx = p1[n], ayy = p1[NN + n], azz = p1[2 * NN + n];
        float bx = g_pcn[b][0][n], by = g_pcn[b][1][n], bz = g_pcn[b][2][n];
        float iax = ind * axx, iay = ind * ayy, iaz = ind * azz;
        P[0] += ind;
        P[1] += iax; P[2] += iay; P[3] += iaz;
        P[4] += ind * bx; P[5] += ind * by; P[6] += ind * bz;
        P[7]  += iax * bx; P[8]  += iax * by; P[9]  += iax * bz;
        P[10] += iay * bx; P[11] += iay * by; P[12] += iay * bz;
        P[13] += iaz * bx; P[14] += iaz * by; P[15] += iaz * bz;
    }
    #pragma unroll
    for (int o = 16; o; o >>= 1)
        #pragma unroll
        for (int i = 0; i < 16; ++i)
            P[i] += __shfl_xor_sync(~0u, P[i], o);
    if (lane == 0) {
        #pragma unroll
        for (int i = 0; i < 16; ++i) smP[w][i] = P[i];
    }
    __syncthreads();
    if (w == 0 && lane < 16) {
        float ssum = 0.f;
        #pragma unroll
        for (int ww = 0; ww < 8; ++ww) ssum += smP[ww][lane];
        g_mpart[b][slice][lane] = ssum;
    }
}

// ---------------------------------------------------------------------------
// Kernel 4: SVD tail per batch (lanes 0-15 parallel-load moments).
// ---------------------------------------------------------------------------
__global__ void cpnet_svd(float* __restrict__ out) {
    const int b = blockIdx.x;
    const int lane = threadIdx.x & 31;

    float Sf = 0.f;
    if (lane < 16) {
        #pragma unroll
        for (int sl = 0; sl < 8; ++sl) Sf += g_mpart[b][sl][lane];
    }
    double S[16];
    #pragma unroll
    for (int i = 0; i < 16; ++i)
        S[i] = (double)__shfl_sync(~0u, Sf, i);

    if (threadIdx.x != 0) return;

    const double sw = S[0];
    const double inv_sw = 1.0 / sw;
    float c1v[3] = {(float)(S[1] * inv_sw), (float)(S[2] * inv_sw), (float)(S[3] * inv_sw)};
    float c2v[3] = {(float)(S[4] * inv_sw), (float)(S[5] * inv_sw), (float)(S[6] * inv_sw)};
    float H[3][3];
    #pragma unroll
    for (int i = 0; i < 3; ++i)
        #pragma unroll
        for (int j = 0; j < 3; ++j)
            H[i][j] = (float)(S[7 + i * 3 + j] - S[1 + i] * S[4 + j] * inv_sw);

    float G[3][3];
    #pragma unroll
    for (int i = 0; i < 3; ++i)
        #pragma unroll
        for (int j = 0; j < 3; ++j)
            G[i][j] = H[0][i] * H[0][j] + H[1][i] * H[1][j] + H[2][i] * H[2][j];
    float V[3][3] = {{1, 0, 0}, {0, 1, 0}, {0, 0, 1}};
    const int PP[3] = {0, 0, 1}, QQ[3] = {1, 2, 2};
    #pragma unroll
    for (int it = 0; it < 18; ++it) {
        int p = PP[it % 3], q = QQ[it % 3];
        float apq = G[p][q];
        if (fabsf(apq) > 1e-25f) {
            float theta = (G[q][q] - G[p][p]) / (2.0f * apq);
            float t = copysignf(1.0f, theta) / (fabsf(theta) + sqrtf(theta * theta + 1.0f));
            float c = rsqrtf(t * t + 1.0f);
            float sn = t * c;
            #pragma unroll
            for (int k = 0; k < 3; ++k) {
                float gkp = G[k][p], gkq = G[k][q];
                G[k][p] = c * gkp - sn * gkq;
                G[k][q] = sn * gkp + c * gkq;
            }
            #pragma unroll
            for (int k = 0; k < 3; ++k) {
                float gpk = G[p][k], gqk = G[q][k];
                G[p][k] = c * gpk - sn * gqk;
                G[q][k] = sn * gpk + c * gqk;
            }
            #pragma unroll
            for (int k = 0; k < 3; ++k) {
                float vkp = V[k][p], vkq = V[k][q];
                V[k][p] = c * vkp - sn * vkq;
                V[k][q] = sn * vkp + c * vkq;
            }
        }
    }
    float ev[3] = {G[0][0], G[1][1], G[2][2]};
    #pragma unroll
    for (int a = 0; a < 2; ++a)
        #pragma unroll
        for (int bc = 1; bc < 3; ++bc)
            if (bc > a && ev[bc] > ev[a]) {
                float te = ev[a]; ev[a] = ev[bc]; ev[bc] = te;
                #pragma unroll
                for (int k = 0; k < 3; ++k) {
                    float tv = V[k][a]; V[k][a] = V[k][bc]; V[k][bc] = tv;
                }
            }
    float U[3][3];
    #pragma unroll
    for (int j = 0; j < 3; ++j) {
        float sig = sqrtf(fmaxf(ev[j], 0.f));
        float inv = (sig > 1e-20f) ? (1.0f / sig) : 0.f;
        #pragma unroll
        for (int i = 0; i < 3; ++i)
            U[i][j] = (H[i][0] * V[0][j] + H[i][1] * V[1][j] + H[i][2] * V[2][j]) * inv;
    }
    auto det3 = [](float M[3][3]) {
        return M[0][0] * (M[1][1] * M[2][2] - M[1][2] * M[2][1])
             - M[0][1] * (M[1][0] * M[2][2] - M[1][2] * M[2][0])
             + M[0][2] * (M[1][0] * M[2][1] - M[1][1] * M[2][0]);
    };
    float sign = (det3(U) * det3(V) < 0.f) ? -1.f : 1.f;
    V[0][2] *= sign; V[1][2] *= sign; V[2][2] *= sign;
    float R[3][3];
    #pragma unroll
    for (int i = 0; i < 3; ++i)
        #pragma unroll
        for (int j = 0; j < 3; ++j)
            R[i][j] = V[i][0] * U[j][0] + V[i][1] * U[j][1] + V[i][2] * U[j][2];
    float tt[3];
    #pragma unroll
    for (int i = 0; i < 3; ++i)
        tt[i] = c2v[i] - (R[i][0] * c1v[0] + R[i][1] * c1v[1] + R[i][2] * c1v[2]);

    float* T = out + b * 16;
    #pragma unroll
    for (int i = 0; i < 3; ++i) {
        T[i * 4 + 0] = R[i][0];
        T[i * 4 + 1] = R[i][1];
        T[i * 4 + 2] = R[i][2];
        T[i * 4 + 3] = tt[i];
    }
    T[12] = 0.f; T[13] = 0.f; T[14] = 0.f; T[15] = 1.f;

    auto sgn = [](float x) { return x >= 0.f ? 1.f : -1.f; };
    float qw = 0.5f * sqrtf(fmaxf(1.f + R[0][0] + R[1][1] + R[2][2], 1e-12f));
    float qx = 0.5f * sqrtf(fmaxf(1.f + R[0][0] - R[1][1] - R[2][2], 1e-12f)) * sgn(R[2][1] - R[1][2]);
    float qy = 0.5f * sqrtf(fmaxf(1.f - R[0][0] + R[1][1] - R[2][2], 1e-12f)) * sgn(R[0][2] - R[2][0]);
    float qz = 0.5f * sqrtf(fmaxf(1.f - R[0][0] - R[1][1] + R[2][2], 1e-12f)) * sgn(R[1][0] - R[0][1]);
    float* qo = out + BB * 16 + b * 4;
    qo[0] = qw; qo[1] = qx; qo[2] = qy; qo[3] = qz;
    float* to = out + BB * 16 + BB * 4 + b * 3;
    to[0] = tt[0]; to[1] = tt[1]; to[2] = tt[2];
}

// ---------------------------------------------------------------------------
extern "C" void kernel_launch(void* const* d_in, const int* in_sizes, int n_in,
                              void* d_out, int out_size) {
    const float* pc1 = (const float*)d_in[0];
    const float* pc2 = (const float*)d_in[1];
    float* out = (float*)d_out;

    cpnet_bin<<<BB, 1024>>>(pc2);
    dim3 rgrid(RCTAS, BB);   // 512 x 8 CTAs, 8 warps = 8 rows each
    cpnet_rows<<<rgrid, 256>>>(pc1, pc2);
    dim3 mgrid(8, BB);
    cpnet_moments<<<mgrid, 256>>>(pc1);
    cpnet_svd<<<BB, 32>>>(out);
}